// round 9
// baseline (speedup 1.0000x reference)
#include <cuda_runtime.h>
#include <cstdint>

// Problem constants (fixed by the dataset)
#define B_  64
#define NH  1024
#define NV  2048

#define THREADS   128
#define H_SPLIT   8
#define HS        (NH / H_SPLIT)      // 128 rows per CTA
#define RB        4                   // rows per load/store burst (32KB each way)
#define CHUNKS    (NV / (THREADS*4))  // 4 float4-chunks cover a full row
#define ROW4      (NV / 4)            // 512 float4 per row

// out layout: [ b2 : B*NV floats ][ wt2 : B*NH*NV floats ]
#define B2_ELEMS  (B_ * NV)

// Scratch: per-(batch, h-chunk) full-NV b2 partials + per-batch tickets.
__device__ float4       g_partial4[(size_t)H_SPLIT * B_ * ROW4];   // 4 MB
__device__ unsigned int g_count[B_];                               // zero-init

// ---------------------------------------------------------------------------
// Single fused kernel, contiguous-slab geometry:
//   CTA (hc, b) owns wt1[b, hc*128:(hc+1)*128, :]  -- a contiguous 1MB slab.
//   wt2 = scale * wt1 streamed through registers in 32KB bursts.
//   b2: per-CTA partial over its 128 rows -> scratch; last ticket per batch
//       reduces 8 partials + b1 and writes b2.
// ---------------------------------------------------------------------------
__global__ __launch_bounds__(THREADS, 4)
void fused_convert_kernel(const float* __restrict__ b1,
                          const float* __restrict__ wt1,
                          const float* __restrict__ muh1,
                          const float* __restrict__ muh2,
                          const float* __restrict__ varh1,
                          const float* __restrict__ varh2,
                          float* __restrict__ out_b2,
                          float* __restrict__ out_wt2) {
    __shared__ float s_scale[HS];
    __shared__ float s_coeff[HS];
    __shared__ unsigned int s_ticket;

    const int hc = blockIdx.x;
    const int b  = blockIdx.y;
    const int h0 = hc * HS;
    const int t  = threadIdx.x;

    // HS == THREADS: one scale/coeff per thread
    {
        const int idx = b * NH + h0 + t;
        const float sc = sqrtf(varh1[idx]) * rsqrtf(varh2[idx]);
        s_scale[t] = sc;
        s_coeff[t] = fmaf(-sc, muh2[idx], muh1[idx]);
    }
    __syncthreads();

    // Contiguous slab base (in float4 units)
    const size_t slab4 = (((size_t)b * NH + h0) * NV) >> 2;
    const float4* __restrict__ src = reinterpret_cast<const float4*>(wt1) + slab4;
    float4*       __restrict__ dst = reinterpret_cast<float4*>(out_wt2) + slab4;

    float4 acc[CHUNKS];
    #pragma unroll
    for (int c = 0; c < CHUNKS; ++c) acc[c] = make_float4(0.f, 0.f, 0.f, 0.f);

    for (int i = 0; i < HS; i += RB) {
        float4 w[RB][CHUNKS];

        // 32KB contiguous read burst (RB rows x 8KB, CTA-aggregate sequential)
        #pragma unroll
        for (int r = 0; r < RB; ++r)
            #pragma unroll
            for (int c = 0; c < CHUNKS; ++c)
                w[r][c] = __ldg(src + (size_t)(i + r) * ROW4 + c * THREADS + t);

        // Compute + 32KB contiguous write burst
        #pragma unroll
        for (int r = 0; r < RB; ++r) {
            const float sc = s_scale[i + r];
            const float cf = s_coeff[i + r];
            #pragma unroll
            for (int c = 0; c < CHUNKS; ++c) {
                acc[c].x = fmaf(w[r][c].x, cf, acc[c].x);
                acc[c].y = fmaf(w[r][c].y, cf, acc[c].y);
                acc[c].z = fmaf(w[r][c].z, cf, acc[c].z);
                acc[c].w = fmaf(w[r][c].w, cf, acc[c].w);

                float4 o;
                o.x = w[r][c].x * sc; o.y = w[r][c].y * sc;
                o.z = w[r][c].z * sc; o.w = w[r][c].w * sc;
                dst[(size_t)(i + r) * ROW4 + c * THREADS + t] = o;
            }
        }
    }

    // ---- store full-NV partial, take a ticket ----
    {
        float4* part = g_partial4 + (size_t)(b * H_SPLIT + hc) * ROW4;
        #pragma unroll
        for (int c = 0; c < CHUNKS; ++c)
            part[c * THREADS + t] = acc[c];
    }
    __threadfence();
    __syncthreads();

    if (t == 0)
        s_ticket = atomicAdd(&g_count[b], 1u);
    __syncthreads();

    if (s_ticket == H_SPLIT - 1) {
        // Last CTA of this batch: b2 = b1 + sum of 8 partials
        const float4* __restrict__ b1v =
            reinterpret_cast<const float4*>(b1) + (size_t)b * ROW4;
        float4* __restrict__ o4 =
            reinterpret_cast<float4*>(out_b2) + (size_t)b * ROW4;

        #pragma unroll
        for (int c = 0; c < CHUNKS; ++c) {
            const int v = c * THREADS + t;
            float4 sum = b1v[v];
            #pragma unroll
            for (int s = 0; s < H_SPLIT; ++s) {
                const float4 p = g_partial4[(size_t)(b * H_SPLIT + s) * ROW4 + v];
                sum.x += p.x; sum.y += p.y; sum.z += p.z; sum.w += p.w;
            }
            o4[v] = sum;
        }

        // Reset ticket for the next graph replay (deterministic)
        if (t == 0) g_count[b] = 0u;
    }
}

// ---------------------------------------------------------------------------
// Launch — single kernel node
// Inputs (metadata order): b1, wt1, muh1, muh2, varh_diag1, varh_diag2
// Output: [b2 | wt2]
// ---------------------------------------------------------------------------
extern "C" void kernel_launch(void* const* d_in, const int* in_sizes, int n_in,
                              void* d_out, int out_size) {
    const float* b1    = (const float*)d_in[0];
    const float* wt1   = (const float*)d_in[1];
    const float* muh1  = (const float*)d_in[2];
    const float* muh2  = (const float*)d_in[3];
    const float* varh1 = (const float*)d_in[4];
    const float* varh2 = (const float*)d_in[5];

    float* out_b2  = (float*)d_out;
    float* out_wt2 = out_b2 + B2_ELEMS;

    dim3 grid(H_SPLIT, B_);
    fused_convert_kernel<<<grid, THREADS>>>(b1, wt1, muh1, muh2, varh1, varh2,
                                            out_b2, out_wt2);
}

// round 10
// speedup vs baseline: 1.1696x; 1.1696x over previous
#include <cuda_runtime.h>
#include <cstdint>

// Problem constants (fixed by the dataset)
#define B_  64
#define NH  1024
#define NV  2048

#define THREADS   128
#define VT        (THREADS * 4)   // 512 v-columns per block (float4 per thread)
#define H_SPLIT   4
#define HS        (NH / H_SPLIT)  // 256 h per block
#define RBATCH    8               // rows staged per load/store burst

// out layout: [ b2 : B*NV floats ][ wt2 : B*NH*NV floats ]
#define B2_ELEMS  (B_ * NV)

// ---------------------------------------------------------------------------
// Kernel 1: seed b2 with b1 (b2 then receives atomic partial sums)
// ---------------------------------------------------------------------------
__global__ void init_b2_kernel(const float* __restrict__ b1,
                               float* __restrict__ out_b2) {
    int i = blockIdx.x * blockDim.x + threadIdx.x;   // float4 index
    const float4* src = reinterpret_cast<const float4*>(b1);
    float4*       dst = reinterpret_cast<float4*>(out_b2);
    if (i < B2_ELEMS / 4) dst[i] = src[i];
}

// ---------------------------------------------------------------------------
// Kernel 2: fused  wt2 = scale * wt1  and  b2 += sum_h coeff[h] * wt1[:,h,:]
//   grid: (NV/VT, H_SPLIT, B) = (4, 4, 64) = 1024 CTAs.
//   __launch_bounds__(128, 7): regs capped at 72 -> 7 CTAs/SM resident,
//   so all 1024 CTAs run in a single wave (needs 6.92/SM).
//   RBATCH=8 row staging: 16KB same-direction bursts per warp group,
//   proven best kernel shape (164.2us @ 79.1% DRAM in R5).
// ---------------------------------------------------------------------------
__global__ __launch_bounds__(THREADS, 7)
void fused_convert_kernel(const float* __restrict__ wt1,
                          const float* __restrict__ muh1,
                          const float* __restrict__ muh2,
                          const float* __restrict__ varh1,
                          const float* __restrict__ varh2,
                          float* __restrict__ out_b2,
                          float* __restrict__ out_wt2) {
    __shared__ float s_scale[HS];
    __shared__ float s_coeff[HS];

    const int b  = blockIdx.z;
    const int h0 = blockIdx.y * HS;
    const int v0 = blockIdx.x * VT + threadIdx.x * 4;

    // Precompute per-h scale and coeff for this h-range
    for (int i = threadIdx.x; i < HS; i += THREADS) {
        const int idx = b * NH + h0 + i;
        const float sc = sqrtf(varh1[idx]) * rsqrtf(varh2[idx]);
        s_scale[i] = sc;
        s_coeff[i] = fmaf(-sc, muh2[idx], muh1[idx]);
    }
    __syncthreads();

    // float4 pointers; h-stride in float4 units is NV/4
    const size_t base = ((size_t)(b * NH + h0) * NV + v0) >> 2;
    const float4* __restrict__ src = reinterpret_cast<const float4*>(wt1) + base;
    float4*       __restrict__ dst = reinterpret_cast<float4*>(out_wt2) + base;
    const int hstride = NV / 4;

    float4 acc = make_float4(0.f, 0.f, 0.f, 0.f);

    for (int i = 0; i < HS; i += RBATCH) {
        float4 w[RBATCH];

        // Burst of RBATCH independent 16B loads (read phase)
        #pragma unroll
        for (int j = 0; j < RBATCH; ++j)
            w[j] = __ldg(src + (size_t)(i + j) * hstride);

        // Compute + burst of RBATCH stores (write phase)
        #pragma unroll
        for (int j = 0; j < RBATCH; ++j) {
            const float sc = s_scale[i + j];
            const float cf = s_coeff[i + j];

            acc.x = fmaf(w[j].x, cf, acc.x);
            acc.y = fmaf(w[j].y, cf, acc.y);
            acc.z = fmaf(w[j].z, cf, acc.z);
            acc.w = fmaf(w[j].w, cf, acc.w);

            float4 o;
            o.x = w[j].x * sc; o.y = w[j].y * sc;
            o.z = w[j].z * sc; o.w = w[j].w * sc;
            dst[(size_t)(i + j) * hstride] = o;
        }
    }

    // Partial b2 contribution from this h-split (REDG, distinct addresses)
    float* b2p = out_b2 + (size_t)b * NV + v0;
    atomicAdd(b2p + 0, acc.x);
    atomicAdd(b2p + 1, acc.y);
    atomicAdd(b2p + 2, acc.z);
    atomicAdd(b2p + 3, acc.w);
}

// ---------------------------------------------------------------------------
// Launch
// Inputs (metadata order): b1, wt1, muh1, muh2, varh_diag1, varh_diag2
// Output: [b2 | wt2]
// ---------------------------------------------------------------------------
extern "C" void kernel_launch(void* const* d_in, const int* in_sizes, int n_in,
                              void* d_out, int out_size) {
    const float* b1    = (const float*)d_in[0];
    const float* wt1   = (const float*)d_in[1];
    const float* muh1  = (const float*)d_in[2];
    const float* muh2  = (const float*)d_in[3];
    const float* varh1 = (const float*)d_in[4];
    const float* varh2 = (const float*)d_in[5];

    float* out_b2  = (float*)d_out;
    float* out_wt2 = out_b2 + B2_ELEMS;

    init_b2_kernel<<<(B2_ELEMS / 4 + 255) / 256, 256>>>(b1, out_b2);

    dim3 grid(NV / VT, H_SPLIT, B_);
    fused_convert_kernel<<<grid, THREADS>>>(wt1, muh1, muh2, varh1, varh2,
                                            out_b2, out_wt2);
}

// round 11
// speedup vs baseline: 1.1705x; 1.0007x over previous
#include <cuda_runtime.h>
#include <cstdint>

// Problem constants (fixed by the dataset)
#define B_  64
#define NH  1024
#define NV  2048

#define THREADS   128
#define VT        (THREADS * 4)   // 512 v-columns per block (float4 per thread)
#define H_SPLIT   4
#define HS        (NH / H_SPLIT)  // 256 h per block
#define RBATCH    8               // rows staged per load/store burst

// out layout: [ b2 : B*NV floats ][ wt2 : B*NH*NV floats ]
#define B2_ELEMS  (B_ * NV)

// ---------------------------------------------------------------------------
// Kernel 1: seed b2 with b1 (b2 then receives atomic partial sums)
// ---------------------------------------------------------------------------
__global__ void init_b2_kernel(const float* __restrict__ b1,
                               float* __restrict__ out_b2) {
    int i = blockIdx.x * blockDim.x + threadIdx.x;   // float4 index
    const float4* src = reinterpret_cast<const float4*>(b1);
    float4*       dst = reinterpret_cast<float4*>(out_b2);
    if (i < B2_ELEMS / 4) dst[i] = src[i];
}

// ---------------------------------------------------------------------------
// Kernel 2: fused  wt2 = scale * wt1  and  b2 += sum_h coeff[h] * wt1[:,h,:]
//   grid: (NV/VT, H_SPLIT, B) = (4, 4, 64) = 1024 CTAs.
//   __launch_bounds__(128, 7): regs capped at 72 -> 7 CTAs/SM resident,
//   all 1024 CTAs in a single wave (needs 6.92/SM).
//   RBATCH=8 staging: 16KB same-direction bursts (best measured shape).
//   Stores use .cs (evict-first): wt2 lines are dead-on-write, keep them
//   from displacing useful L2 state ahead of the wt1 read stream.
// ---------------------------------------------------------------------------
__global__ __launch_bounds__(THREADS, 7)
void fused_convert_kernel(const float* __restrict__ wt1,
                          const float* __restrict__ muh1,
                          const float* __restrict__ muh2,
                          const float* __restrict__ varh1,
                          const float* __restrict__ varh2,
                          float* __restrict__ out_b2,
                          float* __restrict__ out_wt2) {
    __shared__ float s_scale[HS];
    __shared__ float s_coeff[HS];

    const int b  = blockIdx.z;
    const int h0 = blockIdx.y * HS;
    const int v0 = blockIdx.x * VT + threadIdx.x * 4;

    // Precompute per-h scale and coeff for this h-range
    for (int i = threadIdx.x; i < HS; i += THREADS) {
        const int idx = b * NH + h0 + i;
        const float sc = sqrtf(varh1[idx]) * rsqrtf(varh2[idx]);
        s_scale[i] = sc;
        s_coeff[i] = fmaf(-sc, muh2[idx], muh1[idx]);
    }
    __syncthreads();

    // float4 pointers; h-stride in float4 units is NV/4
    const size_t base = ((size_t)(b * NH + h0) * NV + v0) >> 2;
    const float4* __restrict__ src = reinterpret_cast<const float4*>(wt1) + base;
    float4*       __restrict__ dst = reinterpret_cast<float4*>(out_wt2) + base;
    const int hstride = NV / 4;

    float4 acc = make_float4(0.f, 0.f, 0.f, 0.f);

    for (int i = 0; i < HS; i += RBATCH) {
        float4 w[RBATCH];

        // Burst of RBATCH independent 16B loads (read phase)
        #pragma unroll
        for (int j = 0; j < RBATCH; ++j)
            w[j] = __ldg(src + (size_t)(i + j) * hstride);

        // Compute + burst of RBATCH streaming stores (write phase)
        #pragma unroll
        for (int j = 0; j < RBATCH; ++j) {
            const float sc = s_scale[i + j];
            const float cf = s_coeff[i + j];

            acc.x = fmaf(w[j].x, cf, acc.x);
            acc.y = fmaf(w[j].y, cf, acc.y);
            acc.z = fmaf(w[j].z, cf, acc.z);
            acc.w = fmaf(w[j].w, cf, acc.w);

            float4 o;
            o.x = w[j].x * sc; o.y = w[j].y * sc;
            o.z = w[j].z * sc; o.w = w[j].w * sc;
            __stcs(dst + (size_t)(i + j) * hstride, o);
        }
    }

    // Partial b2 contribution from this h-split (REDG, distinct addresses)
    float* b2p = out_b2 + (size_t)b * NV + v0;
    atomicAdd(b2p + 0, acc.x);
    atomicAdd(b2p + 1, acc.y);
    atomicAdd(b2p + 2, acc.z);
    atomicAdd(b2p + 3, acc.w);
}

// ---------------------------------------------------------------------------
// Launch
// Inputs (metadata order): b1, wt1, muh1, muh2, varh_diag1, varh_diag2
// Output: [b2 | wt2]
// ---------------------------------------------------------------------------
extern "C" void kernel_launch(void* const* d_in, const int* in_sizes, int n_in,
                              void* d_out, int out_size) {
    const float* b1    = (const float*)d_in[0];
    const float* wt1   = (const float*)d_in[1];
    const float* muh1  = (const float*)d_in[2];
    const float* muh2  = (const float*)d_in[3];
    const float* varh1 = (const float*)d_in[4];
    const float* varh2 = (const float*)d_in[5];

    float* out_b2  = (float*)d_out;
    float* out_wt2 = out_b2 + B2_ELEMS;

    init_b2_kernel<<<(B2_ELEMS / 4 + 255) / 256, 256>>>(b1, out_b2);

    dim3 grid(NV / VT, H_SPLIT, B_);
    fused_convert_kernel<<<grid, THREADS>>>(wt1, muh1, muh2, varh1, varh2,
                                            out_b2, out_wt2);
}

// round 12
// speedup vs baseline: 1.2003x; 1.0255x over previous
#include <cuda_runtime.h>
#include <cstdint>

// Problem constants (fixed by the dataset)
#define B_  64
#define NH  1024
#define NV  2048

#define THREADS   128
#define VT        (THREADS * 4)   // 512 v-columns per block (float4 per thread)
#define H_SPLIT   4
#define HS        (NH / H_SPLIT)  // 256 h per block

// out layout: [ b2 : B*NV floats ][ wt2 : B*NH*NV floats ]
#define B2_ELEMS  (B_ * NV)

// ---------------------------------------------------------------------------
// Kernel 1: seed b2 with b1 (b2 then receives atomic partial sums)
// ---------------------------------------------------------------------------
__global__ void init_b2_kernel(const float* __restrict__ b1,
                               float* __restrict__ out_b2) {
    int i = blockIdx.x * blockDim.x + threadIdx.x;   // float4 index
    const float4* src = reinterpret_cast<const float4*>(b1);
    float4*       dst = reinterpret_cast<float4*>(out_b2);
    if (i < B2_ELEMS / 4) dst[i] = src[i];
}

// ---------------------------------------------------------------------------
// Kernel 2: fused  wt2 = scale * wt1  and  b2 += sum_h coeff[h] * wt1[:,h,:]
//   grid: (NV/VT, H_SPLIT, B) = (4, 4, 64) = 1024 CTAs, 128 threads, 32 regs.
//   Measured at the mixed-stream HBM plateau (~6.2 TB/s); occupancy, burst
//   shape, and cache hints were all shown to be non-binding (R1-R11).
// ---------------------------------------------------------------------------
__global__ __launch_bounds__(THREADS)
void fused_convert_kernel(const float* __restrict__ wt1,
                          const float* __restrict__ muh1,
                          const float* __restrict__ muh2,
                          const float* __restrict__ varh1,
                          const float* __restrict__ varh2,
                          float* __restrict__ out_b2,
                          float* __restrict__ out_wt2) {
    __shared__ float s_scale[HS];
    __shared__ float s_coeff[HS];

    const int b  = blockIdx.z;
    const int h0 = blockIdx.y * HS;
    const int v0 = blockIdx.x * VT + threadIdx.x * 4;

    // Precompute per-h scale and coeff for this h-range
    for (int i = threadIdx.x; i < HS; i += THREADS) {
        const int idx = b * NH + h0 + i;
        const float sc = sqrtf(varh1[idx]) * rsqrtf(varh2[idx]);
        s_scale[i] = sc;
        s_coeff[i] = fmaf(-sc, muh2[idx], muh1[idx]);
    }
    __syncthreads();

    // float4 pointers; h-stride in float4 units is NV/4
    const size_t base = ((size_t)(b * NH + h0) * NV + v0) >> 2;
    const float4* __restrict__ src = reinterpret_cast<const float4*>(wt1) + base;
    float4*       __restrict__ dst = reinterpret_cast<float4*>(out_wt2) + base;
    const int hstride = NV / 4;

    float4 acc = make_float4(0.f, 0.f, 0.f, 0.f);

    #pragma unroll 4
    for (int i = 0; i < HS; ++i) {
        const float4 w  = __ldg(src + (size_t)i * hstride);
        const float  sc = s_scale[i];
        const float  cf = s_coeff[i];

        acc.x = fmaf(w.x, cf, acc.x);
        acc.y = fmaf(w.y, cf, acc.y);
        acc.z = fmaf(w.z, cf, acc.z);
        acc.w = fmaf(w.w, cf, acc.w);

        float4 o;
        o.x = w.x * sc; o.y = w.y * sc; o.z = w.z * sc; o.w = w.w * sc;
        dst[(size_t)i * hstride] = o;
    }

    // Partial b2 contribution from this h-split (REDG, distinct addresses)
    float* b2p = out_b2 + (size_t)b * NV + v0;
    atomicAdd(b2p + 0, acc.x);
    atomicAdd(b2p + 1, acc.y);
    atomicAdd(b2p + 2, acc.z);
    atomicAdd(b2p + 3, acc.w);
}

// ---------------------------------------------------------------------------
// Launch
// Inputs (metadata order): b1, wt1, muh1, muh2, varh_diag1, varh_diag2
// Output: [b2 | wt2]
// ---------------------------------------------------------------------------
extern "C" void kernel_launch(void* const* d_in, const int* in_sizes, int n_in,
                              void* d_out, int out_size) {
    const float* b1    = (const float*)d_in[0];
    const float* wt1   = (const float*)d_in[1];
    const float* muh1  = (const float*)d_in[2];
    const float* muh2  = (const float*)d_in[3];
    const float* varh1 = (const float*)d_in[4];
    const float* varh2 = (const float*)d_in[5];

    float* out_b2  = (float*)d_out;
    float* out_wt2 = out_b2 + B2_ELEMS;

    init_b2_kernel<<<(B2_ELEMS / 4 + 255) / 256, 256>>>(b1, out_b2);

    dim3 grid(NV / VT, H_SPLIT, B_);
    fused_convert_kernel<<<grid, THREADS>>>(wt1, muh1, muh2, varh1, varh2,
                                            out_b2, out_wt2);
}